// round 1
// baseline (speedup 1.0000x reference)
#include <cuda_runtime.h>

#define BB 8192
#define DD 256
#define TM 64
#define TN 128
#define KC 16
#define NCHUNK (DD/KC)   // 16
#define NT 512

static __device__ float g_an[BB*DD];
static __device__ float g_pn[BB*DD];
static __device__ float g_rowloss[BB];

typedef unsigned long long u64;

__device__ __forceinline__ void ffma2(u64 &d, u64 a, u64 b) {
    asm("fma.rn.f32x2 %0, %1, %2, %0;" : "+l"(d) : "l"(a), "l"(b));
}
__device__ __forceinline__ float2 unpk(u64 v) {
    float2 r;
    asm("mov.b64 {%0, %1}, %2;" : "=f"(r.x), "=f"(r.y) : "l"(v));
    return r;
}

// One block per (row, which-tensor): L2-normalize rows of anchor/positive.
__global__ void nrm_kernel(const float* __restrict__ a, const float* __restrict__ p) {
    int row = blockIdx.x;
    const float* src = blockIdx.y ? p : a;
    float* dst = blockIdx.y ? g_pn : g_an;
    float v = src[row*DD + threadIdx.x];
    float ss = v*v;
    #pragma unroll
    for (int o = 16; o > 0; o >>= 1) ss += __shfl_xor_sync(0xffffffffu, ss, o);
    __shared__ float ws[8];
    if ((threadIdx.x & 31) == 0) ws[threadIdx.x >> 5] = ss;
    __syncthreads();
    float tot = 0.f;
    #pragma unroll
    for (int i = 0; i < 8; ++i) tot += ws[i];
    float scale = 1.0f / fmaxf(sqrtf(tot), 1e-12f);
    dst[row*DD + threadIdx.x] = v * scale;
}

// Fused sim-GEMM + per-row (sumexp, off-diag max, diag) reduction.
// Block: 512 threads = 16(ty) x 32(tx), tile 64 rows x 128 cols, 4x4 micro-tile.
// A stored DUPLICATED in smem ([k][2r]=[k][2r+1]) so FFMA2 operands need no packing MOVs.
__global__ __launch_bounds__(NT, 1)
void fused_kernel() {
    __shared__ __align__(16) float Adup[2][KC*TN];  // [k][2*r] duplicated, width 128
    __shared__ __align__(16) float Psk [2][KC*TN];  // [k][c],   width 128

    const int tid = threadIdx.x;
    const int tx = tid & 31;
    const int ty = tid >> 5;           // 0..15
    const int R0 = blockIdx.x * TM;

    const bool aAct = tid < 256;       // 256 float4 loads cover the A chunk
    const int ar  = tid & 63;
    const int akg = (tid >> 6) & 3;
    const int pc  = tid & 127;
    const int pkg = tid >> 7;          // 0..3

    const float* aBase = g_an + (size_t)(R0 + ar)*DD + akg*4;

    const float NEGINF = __int_as_float(0xff800000);
    const float INVT = 1.0f/0.07f;

    float sum[4], mx[4], dg[4];
    #pragma unroll
    for (int i = 0; i < 4; ++i) { sum[i]=0.f; mx[i]=NEGINF; dg[i]=NEGINF; }

    #pragma unroll 1
    for (int ct = 0; ct < BB/TN; ++ct) {
        const int C0 = ct * TN;
        const float* pBase = g_pn + (size_t)(C0 + pc)*DD + pkg*4;

        u64 acc[8];
        #pragma unroll
        for (int i = 0; i < 8; ++i) acc[i] = 0ull;

        // prologue: chunk 0 -> buf 0
        {
            float4 na, np;
            if (aAct) na = *(const float4*)(aBase);
            np = *(const float4*)(pBase);
            if (aAct) {
                #pragma unroll
                for (int j = 0; j < 4; ++j) {
                    float v = (&na.x)[j];
                    Adup[0][(akg*4 + j)*TN + 2*ar    ] = v;
                    Adup[0][(akg*4 + j)*TN + 2*ar + 1] = v;
                }
            }
            #pragma unroll
            for (int j = 0; j < 4; ++j)
                Psk[0][(pkg*4 + j)*TN + pc] = (&np.x)[j];
        }
        __syncthreads();

        #pragma unroll 1
        for (int kc = 0; kc < NCHUNK; ++kc) {
            const int cur = kc & 1;
            float4 na, np;
            const bool more = (kc + 1) < NCHUNK;
            if (more) {
                if (aAct) na = *(const float4*)(aBase + (kc+1)*KC);
                np = *(const float4*)(pBase + (kc+1)*KC);
            }
            #pragma unroll
            for (int k = 0; k < KC; ++k) {
                ulonglong2 a01 = *(const ulonglong2*)&Adup[cur][k*TN + 8*ty];
                ulonglong2 a23 = *(const ulonglong2*)&Adup[cur][k*TN + 8*ty + 4];
                ulonglong2 pp  = *(const ulonglong2*)&Psk [cur][k*TN + 4*tx];
                ffma2(acc[0], a01.x, pp.x); ffma2(acc[1], a01.x, pp.y);
                ffma2(acc[2], a01.y, pp.x); ffma2(acc[3], a01.y, pp.y);
                ffma2(acc[4], a23.x, pp.x); ffma2(acc[5], a23.x, pp.y);
                ffma2(acc[6], a23.y, pp.x); ffma2(acc[7], a23.y, pp.y);
            }
            if (more) {
                const int nb = cur ^ 1;
                if (aAct) {
                    #pragma unroll
                    for (int j = 0; j < 4; ++j) {
                        float v = (&na.x)[j];
                        Adup[nb][(akg*4 + j)*TN + 2*ar    ] = v;
                        Adup[nb][(akg*4 + j)*TN + 2*ar + 1] = v;
                    }
                }
                #pragma unroll
                for (int j = 0; j < 4; ++j)
                    Psk[nb][(pkg*4 + j)*TN + pc] = (&np.x)[j];
            }
            __syncthreads();
        }

        // epilogue: fold this 64x128 sim tile into per-row streaming stats
        #pragma unroll
        for (int i = 0; i < 4; ++i) {
            const int row = R0 + ty*4 + i;
            #pragma unroll
            for (int pr = 0; pr < 2; ++pr) {
                float2 v = unpk(acc[i*2 + pr]);
                int c0 = C0 + tx*4 + pr*2;
                float e0 = __expf((v.x - 1.0f) * INVT);
                sum[i] += e0;
                if (c0 == row) dg[i] = v.x; else mx[i] = fmaxf(mx[i], v.x);
                float e1 = __expf((v.y - 1.0f) * INVT);
                sum[i] += e1;
                if (c0 + 1 == row) dg[i] = v.y; else mx[i] = fmaxf(mx[i], v.y);
            }
        }
    }

    // per-warp reduction: each warp (fixed ty) owns the same 4 rows across all tx
    #pragma unroll
    for (int i = 0; i < 4; ++i) {
        float s = sum[i], m = mx[i], d = dg[i];
        #pragma unroll
        for (int o = 16; o > 0; o >>= 1) {
            s += __shfl_xor_sync(0xffffffffu, s, o);
            m = fmaxf(m, __shfl_xor_sync(0xffffffffu, m, o));
            d = fmaxf(d, __shfl_xor_sync(0xffffffffu, d, o));
        }
        if (tx == 0) {
            // logsumexp = 1/T + log( sum_j exp((s_ij-1)/T) + exp((m_i-1)/T) )
            float total = s + __expf((m - 1.0f) * INVT);
            g_rowloss[R0 + ty*4 + i] = INVT * (1.0f - d) + logf(total);
        }
    }
}

__global__ void finalize_kernel(float* out) {
    __shared__ double sm[256];
    double s = 0.0;
    for (int i = threadIdx.x; i < BB; i += 256) s += (double)g_rowloss[i];
    sm[threadIdx.x] = s;
    __syncthreads();
    for (int st = 128; st > 0; st >>= 1) {
        if (threadIdx.x < st) sm[threadIdx.x] += sm[threadIdx.x + st];
        __syncthreads();
    }
    if (threadIdx.x == 0) out[0] = (float)(sm[0] / (double)BB);
}

extern "C" void kernel_launch(void* const* d_in, const int* in_sizes, int n_in,
                              void* d_out, int out_size) {
    const float* anchor   = (const float*)d_in[0];
    const float* positive = (const float*)d_in[1];
    nrm_kernel<<<dim3(BB, 2), DD>>>(anchor, positive);
    fused_kernel<<<BB/TM, NT>>>();
    finalize_kernel<<<1, 256>>>((float*)d_out);
}

// round 3
// speedup vs baseline: 8.8974x; 8.8974x over previous
#include <cuda_runtime.h>
#include <cuda_fp16.h>
#include <cstdint>

#define BB 8192
#define DD 256
#define TM 128
#define TN 128
#define NSPLIT 2
#define CPS (BB/NSPLIT)     // 4096 cols per split
#define TT (CPS/TN)         // 32 tiles

static __device__ __half g_a16[BB*DD];
static __device__ __half g_p16[BB*DD];
static __device__ float g_psum[NSPLIT][BB];
static __device__ float g_pmax[NSPLIT][BB];
static __device__ float g_diag[BB];

// dynamic smem: A @0 (64KB), P0 @64KB, P1 @128KB. Stats arrays alias A at the end.
#define SM_A  0u
#define SM_P0 65536u
#define SM_P1 131072u
#define SMEM_BYTES (3*65536)

#define INVT (1.0f/0.07f)
// exp((v-1)/T) = 2^(v*C1 - C1),  C1 = (1/T)*log2(e)
#define C1F 20.609929155556627f

__device__ __forceinline__ uint32_t s2u(const void* p) {
    uint32_t r;
    asm("{ .reg .u64 t; cvta.to.shared.u64 t, %1; cvt.u32.u64 %0, t; }" : "=r"(r) : "l"(p));
    return r;
}

// Load a 128x256 fp16 tile (64KB) into smem with per-row xor swizzle:
// row stride 512B = 32 chunks of 16B; chunk' = chunk ^ (row & 7).
__device__ __forceinline__ void load_tile(uint32_t s_dst, const __half* gtile, int tid) {
    const int row = tid >> 1;
    const int h   = tid & 1;
    const char* src = (const char*)(gtile + (size_t)row * DD) + h * 256;
    const uint32_t rbase = s_dst + (uint32_t)row * 512u;
    const uint32_t rx = (uint32_t)(row & 7);
    #pragma unroll
    for (int j = 0; j < 16; ++j) {
        uint32_t chunk = (uint32_t)(h * 16 + j);
        uint32_t d = rbase + ((chunk ^ rx) << 4);
        asm volatile("cp.async.cg.shared.global [%0], [%1], 16;"
                     :: "r"(d), "l"(src + j * 16));
    }
}

#define LDSM_X4(r0, r1, r2, r3, addr) \
    asm volatile("ldmatrix.sync.aligned.m8n8.x4.shared.b16 {%0,%1,%2,%3}, [%4];" \
                 : "=r"(r0), "=r"(r1), "=r"(r2), "=r"(r3) : "r"(addr))

#define MMA16816(c, a, b0v, b1v) \
    asm volatile("mma.sync.aligned.m16n8k16.row.col.f32.f16.f16.f32 " \
                 "{%0,%1,%2,%3}, {%4,%5,%6,%7}, {%8,%9}, {%0,%1,%2,%3};" \
                 : "+f"((c)[0]), "+f"((c)[1]), "+f"((c)[2]), "+f"((c)[3]) \
                 : "r"((a)[0]), "r"((a)[1]), "r"((a)[2]), "r"((a)[3]), \
                   "r"(b0v), "r"(b1v))

// Warp-per-row: L2-normalize fp32 row -> fp16 row.
__global__ void nrm_kernel(const float* __restrict__ a, const float* __restrict__ p) {
    int lane = threadIdx.x & 31;
    int row = blockIdx.x * 16 + (threadIdx.x >> 5);
    const float* src = (blockIdx.y ? p : a) + (size_t)row * DD + lane * 8;
    float4 v0 = *(const float4*)src;
    float4 v1 = *(const float4*)(src + 4);
    float ss = v0.x*v0.x + v0.y*v0.y + v0.z*v0.z + v0.w*v0.w
             + v1.x*v1.x + v1.y*v1.y + v1.z*v1.z + v1.w*v1.w;
    #pragma unroll
    for (int o = 16; o > 0; o >>= 1) ss += __shfl_xor_sync(0xffffffffu, ss, o);
    float sc = 1.0f / fmaxf(sqrtf(ss), 1e-12f);
    __half2 h[4];
    h[0] = __floats2half2_rn(v0.x*sc, v0.y*sc);
    h[1] = __floats2half2_rn(v0.z*sc, v0.w*sc);
    h[2] = __floats2half2_rn(v1.x*sc, v1.y*sc);
    h[3] = __floats2half2_rn(v1.z*sc, v1.w*sc);
    __half* dst = (blockIdx.y ? g_p16 : g_a16) + (size_t)row * DD + lane * 8;
    *(uint4*)dst = *(const uint4*)h;
}

__global__ __launch_bounds__(256, 1) void fused_kernel() {
    extern __shared__ char smem[];
    const uint32_t sb = s2u(smem);
    const int tid = threadIdx.x;
    const int lane = tid & 31, wid = tid >> 5;
    const int warp_m = wid >> 2;          // 0..1
    const int warp_n = wid & 3;           // 0..3
    const int bx = blockIdx.x, s = blockIdx.y;
    const int R0 = bx * TM;
    const int CB = s * CPS;

    // Prologue: A resident + P tiles 0,1
    load_tile(sb + SM_A,  g_a16 + (size_t)R0 * DD, tid);
    load_tile(sb + SM_P0, g_p16 + (size_t)CB * DD, tid);
    asm volatile("cp.async.commit_group;");
    load_tile(sb + SM_P1, g_p16 + (size_t)(CB + TN) * DD, tid);
    asm volatile("cp.async.commit_group;");

    // ldmatrix per-thread addressing invariants
    const uint32_t lrow  = (uint32_t)(lane & 15);
    const uint32_t khalf = (uint32_t)(lane >> 4);
    const uint32_t xorp  = (uint32_t)(lane & 7);

    uint32_t aBase[4];
    #pragma unroll
    for (int mf = 0; mf < 4; ++mf)
        aBase[mf] = sb + SM_A + (uint32_t)(warp_m*64 + mf*16 + (int)lrow) * 512u;

    const float NEGINF = __int_as_float(0xff800000);
    float sum[4][2], mx[4][2], dg[4][2];
    #pragma unroll
    for (int mf = 0; mf < 4; ++mf)
        #pragma unroll
        for (int h = 0; h < 2; ++h) { sum[mf][h]=0.f; mx[mf][h]=NEGINF; dg[mf][h]=0.f; }

    int grow[4][2];
    #pragma unroll
    for (int mf = 0; mf < 4; ++mf)
        #pragma unroll
        for (int h = 0; h < 2; ++h)
            grow[mf][h] = R0 + warp_m*64 + mf*16 + (lane >> 2) + 8*h;

    #pragma unroll 1
    for (int t = 0; t < TT; ++t) {
        if (t + 1 < TT) asm volatile("cp.async.wait_group 1;");
        else            asm volatile("cp.async.wait_group 0;");
        __syncthreads();

        const uint32_t pb = (t & 1) ? SM_P1 : SM_P0;
        uint32_t bBase[2];
        #pragma unroll
        for (int nfp = 0; nfp < 2; ++nfp)
            bBase[nfp] = sb + pb + (uint32_t)(warp_n*32 + nfp*16 + (int)lrow) * 512u;

        float acc[4][4][4];
        #pragma unroll
        for (int mf = 0; mf < 4; ++mf)
            #pragma unroll
            for (int nf = 0; nf < 4; ++nf)
                #pragma unroll
                for (int e = 0; e < 4; ++e) acc[mf][nf][e] = 0.f;

        #pragma unroll
        for (int ks = 0; ks < 16; ++ks) {
            const uint32_t coff = (((uint32_t)(2*ks) + khalf) ^ xorp) << 4;
            uint32_t a[4][4];
            #pragma unroll
            for (int mf = 0; mf < 4; ++mf)
                LDSM_X4(a[mf][0], a[mf][1], a[mf][2], a[mf][3], aBase[mf] + coff);
            uint32_t b[2][4];
            #pragma unroll
            for (int nfp = 0; nfp < 2; ++nfp)
                LDSM_X4(b[nfp][0], b[nfp][1], b[nfp][2], b[nfp][3], bBase[nfp] + coff);
            #pragma unroll
            for (int mf = 0; mf < 4; ++mf) {
                MMA16816(acc[mf][0], a[mf], b[0][0], b[0][2]);
                MMA16816(acc[mf][1], a[mf], b[0][1], b[0][3]);
                MMA16816(acc[mf][2], a[mf], b[1][0], b[1][2]);
                MMA16816(acc[mf][3], a[mf], b[1][1], b[1][3]);
            }
        }

        // Epilogue: fold this 128x128 tile into per-row streaming stats
        const int cb0 = CB + t*TN + warp_n*32 + (lane & 3)*2;
        #pragma unroll
        for (int mf = 0; mf < 4; ++mf) {
            #pragma unroll
            for (int h = 0; h < 2; ++h) {
                const int r = grow[mf][h];
                float lsum = 0.f;
                #pragma unroll
                for (int nf = 0; nf < 4; ++nf) {
                    #pragma unroll
                    for (int e = 0; e < 2; ++e) {
                        float v = acc[mf][nf][h*2 + e];
                        float ex;
                        asm("ex2.approx.f32 %0, %1;" : "=f"(ex) : "f"(fmaf(v, C1F, -C1F)));
                        lsum += ex;
                        bool isd = ((cb0 + nf*8 + e) == r);
                        mx[mf][h] = fmaxf(mx[mf][h], isd ? NEGINF : v);
                        if (isd) dg[mf][h] = v;
                    }
                }
                sum[mf][h] += lsum;
            }
        }

        __syncthreads();
        if (t + 2 < TT) {
            load_tile(sb + pb, g_p16 + (size_t)(CB + (t + 2) * TN) * DD, tid);
            asm volatile("cp.async.commit_group;");
        }
    }

    // Quad reduction (lanes 4q..4q+3 share the same rows)
    #pragma unroll
    for (int mf = 0; mf < 4; ++mf) {
        #pragma unroll
        for (int h = 0; h < 2; ++h) {
            #pragma unroll
            for (int o = 1; o < 4; o <<= 1) {
                sum[mf][h] += __shfl_xor_sync(0xffffffffu, sum[mf][h], o);
                mx[mf][h]  = fmaxf(mx[mf][h], __shfl_xor_sync(0xffffffffu, mx[mf][h], o));
                dg[mf][h]  += __shfl_xor_sync(0xffffffffu, dg[mf][h], o);
            }
        }
    }

    // Cross-warp_n combine via smem (aliases dead A region)
    float* sSum = (float*)smem;          // [4][128]
    float* sMax = sSum + 512;
    float* sDg  = sMax + 512;
    if ((lane & 3) == 0) {
        #pragma unroll
        for (int mf = 0; mf < 4; ++mf) {
            #pragma unroll
            for (int h = 0; h < 2; ++h) {
                int rl = warp_m*64 + mf*16 + (lane >> 2) + 8*h;
                sSum[warp_n*128 + rl] = sum[mf][h];
                sMax[warp_n*128 + rl] = mx[mf][h];
                sDg [warp_n*128 + rl] = dg[mf][h];
            }
        }
    }
    __syncthreads();
    if (tid < 128) {
        float S = 0.f, M = NEGINF, D = 0.f;
        #pragma unroll
        for (int w = 0; w < 4; ++w) {
            S += sSum[w*128 + tid];
            M = fmaxf(M, sMax[w*128 + tid]);
            D += sDg[w*128 + tid];
        }
        g_psum[s][R0 + tid] = S;
        g_pmax[s][R0 + tid] = M;
        if ((bx >> 5) == s) g_diag[R0 + tid] = D;
    }
}

__global__ void finalize_kernel(float* out) {
    __shared__ double sm[256];
    double sloc = 0.0;
    for (int i = threadIdx.x; i < BB; i += 256) {
        float sum = g_psum[0][i] + g_psum[1][i];
        float m = fmaxf(g_pmax[0][i], g_pmax[1][i]);
        float total = sum + __expf((m - 1.0f) * INVT);
        sloc += (double)(INVT * (1.0f - g_diag[i]) + logf(total));
    }
    sm[threadIdx.x] = sloc;
    __syncthreads();
    for (int st = 128; st > 0; st >>= 1) {
        if (threadIdx.x < st) sm[threadIdx.x] += sm[threadIdx.x + st];
        __syncthreads();
    }
    if (threadIdx.x == 0) out[0] = (float)(sm[0] / (double)BB);
}

extern "C" void kernel_launch(void* const* d_in, const int* in_sizes, int n_in,
                              void* d_out, int out_size) {
    const float* anchor   = (const float*)d_in[0];
    const float* positive = (const float*)d_in[1];
    cudaFuncSetAttribute(fused_kernel, cudaFuncAttributeMaxDynamicSharedMemorySize, SMEM_BYTES);
    nrm_kernel<<<dim3(BB/16, 2), 512>>>(anchor, positive);
    fused_kernel<<<dim3(BB/TM, NSPLIT), 256, SMEM_BYTES>>>();
    finalize_kernel<<<1, 256>>>((float*)d_out);
}